// round 3
// baseline (speedup 1.0000x reference)
#include <cuda_runtime.h>
#include <cuda_bf16.h>

// yolov8_GradCamLoss: out = sum(x0) + sum(x1) + sum(x2)
// Pure HBM-bound: 225.8 MB fp32 read -> 1 scalar. Roofline ~28 us @ 8 TB/s.
// R2: 38.9us total, DRAM 74.4%. R3: single kernel (drop zero-kernel overhead),
// unroll-4 batched LDG.128 for MLP=4, __ldcs streaming hint, last-block finish.

#define NBLOCKS (148 * 8)

__device__ float        g_partials[NBLOCKS];
__device__ unsigned int g_arrive = 0;

__device__ __forceinline__ float sum4(float4 v) {
    return (v.x + v.y) + (v.z + v.w);
}

// Grid-stride sum over one tensor with 4 independent LDG.128 in flight.
__device__ __forceinline__ float strided_sum(const float4* __restrict__ p,
                                             long long n4, long long tid,
                                             long long stride)
{
    float s0 = 0.f, s1 = 0.f, s2 = 0.f, s3 = 0.f;
    long long i = tid;
    for (; i + 3 * stride < n4; i += 4 * stride) {
        float4 v0 = __ldcs(p + i);
        float4 v1 = __ldcs(p + i + stride);
        float4 v2 = __ldcs(p + i + 2 * stride);
        float4 v3 = __ldcs(p + i + 3 * stride);
        s0 += sum4(v0);
        s1 += sum4(v1);
        s2 += sum4(v2);
        s3 += sum4(v3);
    }
    for (; i < n4; i += stride)
        s0 += sum4(__ldcs(p + i));
    return (s0 + s1) + (s2 + s3);
}

__global__ __launch_bounds__(256) void sum3_kernel(
    const float4* __restrict__ a, long long na4,
    const float4* __restrict__ b, long long nb4,
    const float4* __restrict__ c, long long nc4,
    float* __restrict__ out)
{
    const long long tid    = (long long)blockIdx.x * blockDim.x + threadIdx.x;
    const long long stride = (long long)gridDim.x * blockDim.x;

    float s = strided_sum(a, na4, tid, stride)
            + strided_sum(b, nb4, tid, stride)
            + strided_sum(c, nc4, tid, stride);

    // Warp reduction
    #pragma unroll
    for (int off = 16; off > 0; off >>= 1)
        s += __shfl_xor_sync(0xFFFFFFFFu, s, off);

    __shared__ float warp_sums[8];
    __shared__ bool  is_last;
    const int lane = threadIdx.x & 31;
    const int wid  = threadIdx.x >> 5;
    if (lane == 0) warp_sums[wid] = s;
    __syncthreads();

    if (wid == 0) {
        s = (lane < 8) ? warp_sums[lane] : 0.0f;
        #pragma unroll
        for (int off = 4; off > 0; off >>= 1)
            s += __shfl_xor_sync(0xFFFFFFFFu, s, off);
        if (lane == 0) {
            g_partials[blockIdx.x] = s;
            __threadfence();
            unsigned int t = atomicAdd(&g_arrive, 1u);
            is_last = (t == gridDim.x - 1);
        }
    }
    __syncthreads();

    // Last block to arrive reduces all partials and writes the scalar.
    if (is_last) {
        float r = 0.0f;
        for (int i = threadIdx.x; i < gridDim.x; i += blockDim.x)
            r += g_partials[i];
        #pragma unroll
        for (int off = 16; off > 0; off >>= 1)
            r += __shfl_xor_sync(0xFFFFFFFFu, r, off);
        if (lane == 0) warp_sums[wid] = r;
        __syncthreads();
        if (wid == 0) {
            r = (lane < 8) ? warp_sums[lane] : 0.0f;
            #pragma unroll
            for (int off = 4; off > 0; off >>= 1)
                r += __shfl_xor_sync(0xFFFFFFFFu, r, off);
            if (lane == 0) {
                out[0] = r;
                g_arrive = 0;   // reset for next graph replay
            }
        }
    }
}

extern "C" void kernel_launch(void* const* d_in, const int* in_sizes, int n_in,
                              void* d_out, int out_size)
{
    const float* x0 = (const float*)d_in[0];
    const float* x1 = (const float*)d_in[1];
    const float* x2 = (const float*)d_in[2];
    float* out = (float*)d_out;

    const long long n0_4 = (long long)in_sizes[0] >> 2;  // 10,752,000
    const long long n1_4 = (long long)in_sizes[1] >> 2;  //  2,688,000
    const long long n2_4 = (long long)in_sizes[2] >> 2;  //    672,000

    sum3_kernel<<<NBLOCKS, 256>>>(
        (const float4*)x0, n0_4,
        (const float4*)x1, n1_4,
        (const float4*)x2, n2_4,
        out);
}

// round 4
// speedup vs baseline: 1.0515x; 1.0515x over previous
#include <cuda_runtime.h>
#include <cuda_bf16.h>

// yolov8_GradCamLoss: out = sum(x0) + sum(x1) + sum(x2)
// Pure HBM-bound: 225.8 MB fp32 read -> 1 scalar. Roofline ~28 us @ 8 TB/s.
// R2: 38.9us (split kernels, DRAM 74.4%, 32 regs, occ 99%).
// R3: 43.1us REGRESSION (unroll-4 w/ i64 idx -> 46 regs -> occ 53.5%).
// R4: unroll-4 + int32 indices + __launch_bounds__(256,8) to pin 32 regs,
//     single kernel w/ last-block finish.

#define NBLOCKS (148 * 8)

__device__ float        g_partials[NBLOCKS];
__device__ unsigned int g_arrive = 0;

__device__ __forceinline__ float sum4(float4 v) {
    return (v.x + v.y) + (v.z + v.w);
}

// Grid-stride sum with 4 independent LDG.128 in flight. int32 indexing.
__device__ __forceinline__ float strided_sum(const float4* __restrict__ p,
                                             int n4, int tid, int stride)
{
    float s0 = 0.f, s1 = 0.f, s2 = 0.f, s3 = 0.f;
    int i = tid;
    const int stride4 = stride * 4;
    for (; i + 3 * stride < n4; i += stride4) {
        float4 v0 = p[i];
        float4 v1 = p[i + stride];
        float4 v2 = p[i + 2 * stride];
        float4 v3 = p[i + 3 * stride];
        s0 += sum4(v0);
        s1 += sum4(v1);
        s2 += sum4(v2);
        s3 += sum4(v3);
    }
    for (; i < n4; i += stride)
        s0 += sum4(p[i]);
    return (s0 + s1) + (s2 + s3);
}

__global__ __launch_bounds__(256, 8) void sum3_kernel(
    const float4* __restrict__ a, int na4,
    const float4* __restrict__ b, int nb4,
    const float4* __restrict__ c, int nc4,
    float* __restrict__ out)
{
    const int tid    = blockIdx.x * blockDim.x + threadIdx.x;
    const int stride = gridDim.x * blockDim.x;

    float s = strided_sum(a, na4, tid, stride)
            + strided_sum(b, nb4, tid, stride)
            + strided_sum(c, nc4, tid, stride);

    // Warp reduction
    #pragma unroll
    for (int off = 16; off > 0; off >>= 1)
        s += __shfl_xor_sync(0xFFFFFFFFu, s, off);

    __shared__ float warp_sums[8];
    __shared__ bool  is_last;
    const int lane = threadIdx.x & 31;
    const int wid  = threadIdx.x >> 5;
    if (lane == 0) warp_sums[wid] = s;
    __syncthreads();

    if (wid == 0) {
        s = (lane < 8) ? warp_sums[lane] : 0.0f;
        #pragma unroll
        for (int off = 4; off > 0; off >>= 1)
            s += __shfl_xor_sync(0xFFFFFFFFu, s, off);
        if (lane == 0) {
            g_partials[blockIdx.x] = s;
            __threadfence();
            unsigned int t = atomicAdd(&g_arrive, 1u);
            is_last = (t == gridDim.x - 1);
        }
    }
    __syncthreads();

    // Last block to arrive reduces all partials and writes the scalar.
    if (is_last) {
        float r = 0.0f;
        for (int i = threadIdx.x; i < (int)gridDim.x; i += blockDim.x)
            r += g_partials[i];
        #pragma unroll
        for (int off = 16; off > 0; off >>= 1)
            r += __shfl_xor_sync(0xFFFFFFFFu, r, off);
        if (lane == 0) warp_sums[wid] = r;
        __syncthreads();
        if (wid == 0) {
            r = (lane < 8) ? warp_sums[lane] : 0.0f;
            #pragma unroll
            for (int off = 4; off > 0; off >>= 1)
                r += __shfl_xor_sync(0xFFFFFFFFu, r, off);
            if (lane == 0) {
                out[0] = r;
                g_arrive = 0;   // reset for next graph replay
            }
        }
    }
}

extern "C" void kernel_launch(void* const* d_in, const int* in_sizes, int n_in,
                              void* d_out, int out_size)
{
    const float* x0 = (const float*)d_in[0];
    const float* x1 = (const float*)d_in[1];
    const float* x2 = (const float*)d_in[2];
    float* out = (float*)d_out;

    const int n0_4 = in_sizes[0] >> 2;  // 10,752,000
    const int n1_4 = in_sizes[1] >> 2;  //  2,688,000
    const int n2_4 = in_sizes[2] >> 2;  //    672,000

    sum3_kernel<<<NBLOCKS, 256>>>(
        (const float4*)x0, n0_4,
        (const float4*)x1, n1_4,
        (const float4*)x2, n2_4,
        out);
}